// round 2
// baseline (speedup 1.0000x reference)
#include <cuda_runtime.h>

#define TS 512
#define BSZ 8
#define FF 1024
#define GG 4096      // 4F
#define VV 32000
#define MM (BSZ*TS)  // 4096
#define NB 128       // persistent scan blocks (<= SM count, 1 block/SM via smem)

// ---------------- scratch (device globals: no runtime allocation) -------------
__device__ float g_xw[(size_t)MM * GG];   // 64 MB: precomputed x@Wx + b
__device__ float g_hs[(size_t)MM * FF];   // 16 MB: hidden states per (b,t)
__device__ float g_h[2][BSZ][FF];         // ping-pong hidden state
__device__ unsigned g_count;              // barrier arrival counter
__device__ unsigned g_gen;                // barrier generation

// ---------------- generic fp32 SGEMM: C[M,N] = A[M,K] @ B[K,N] + bias ---------
// If tokens != nullptr, row m of A is embed[tokens[m], :] (gather).
// 128x128 tile, Ktile=8, 256 threads, 8x8 register microtile (split 4+4 mapping
// so shared loads are conflict-free), register prefetch of next K-tile.
__global__ void sgemm128(const float* __restrict__ A,
                         const int*   __restrict__ tokens,
                         const float* __restrict__ embed,
                         const float* __restrict__ Bm,
                         const float* __restrict__ bias,
                         float* __restrict__ C,
                         int M, int N, int K)
{
    __shared__ float As[8][128];
    __shared__ float Bs[8][128];
    const int tid = threadIdx.x;
    const int bn = blockIdx.x * 128;
    const int bm = blockIdx.y * 128;
    const int tm = tid >> 4;          // 0..15
    const int tn = tid & 15;          // 0..15

    const int arow = tid >> 1;        // 0..127
    const int ak   = (tid & 1) << 2;  // 0 or 4
    const int brow = tid >> 5;        // 0..7
    const int bcol = (tid & 31) << 2; // 0..124

    const float* Arow = tokens
        ? (embed + (size_t)tokens[bm + arow] * K)
        : (A + (size_t)(bm + arow) * K);
    const float* Bptr = Bm + (size_t)brow * N + bn + bcol;

    float acc[8][8];
    #pragma unroll
    for (int i = 0; i < 8; i++)
        #pragma unroll
        for (int j = 0; j < 8; j++) acc[i][j] = 0.f;

    float4 av = *(const float4*)(Arow + ak);
    float4 bv = *(const float4*)(Bptr);

    for (int kt = 0; kt < K; kt += 8) {
        As[ak+0][arow] = av.x; As[ak+1][arow] = av.y;
        As[ak+2][arow] = av.z; As[ak+3][arow] = av.w;
        *(float4*)&Bs[brow][bcol] = bv;
        __syncthreads();
        if (kt + 8 < K) {
            av = *(const float4*)(Arow + kt + 8 + ak);
            bv = *(const float4*)(Bptr + (size_t)(kt + 8) * N);
        }
        #pragma unroll
        for (int kk = 0; kk < 8; ++kk) {
            float a[8], b[8];
            *(float4*)(a)     = *(const float4*)&As[kk][tm * 4];
            *(float4*)(a + 4) = *(const float4*)&As[kk][64 + tm * 4];
            *(float4*)(b)     = *(const float4*)&Bs[kk][tn * 4];
            *(float4*)(b + 4) = *(const float4*)&Bs[kk][64 + tn * 4];
            #pragma unroll
            for (int i = 0; i < 8; i++)
                #pragma unroll
                for (int j = 0; j < 8; j++)
                    acc[i][j] += a[i] * b[j];
        }
        __syncthreads();
    }

    #pragma unroll
    for (int i = 0; i < 8; i++) {
        int row = bm + ((i < 4) ? (tm * 4 + i) : (64 + tm * 4 + (i - 4)));
        float* Cr = C + (size_t)row * N + bn;
        #pragma unroll
        for (int jh = 0; jh < 2; ++jh) {
            int col0 = jh * 64 + tn * 4;
            float4 v;
            v.x = acc[i][jh*4+0] + bias[bn + col0 + 0];
            v.y = acc[i][jh*4+1] + bias[bn + col0 + 1];
            v.z = acc[i][jh*4+2] + bias[bn + col0 + 2];
            v.w = acc[i][jh*4+3] + bias[bn + col0 + 3];
            *(float4*)(Cr + col0) = v;
        }
    }
}

// ---------------- persistent LSTM scan ---------------------------------------
// 128 blocks x 256 threads, 1 block/SM (165.8KB smem). Block bk owns features
// [bk*8, bk*8+8) -> 32 gate columns {g*1024 + f} resident in SMEM for all 512
// steps. One global barrier per step; h double-buffered in global.
#define SMEM_FLOATS (32*1028 + 8*1028 + 256 + 64)
#define SMEM_BYTES  (SMEM_FLOATS * 4)

__global__ void __launch_bounds__(256, 1) lstm_scan(const float* __restrict__ Wh)
{
    extern __shared__ float sm[];
    float* whs = sm;                     // [32][1028] Wh slice, padded rows
    float* h_s = sm + 32 * 1028;         // [8][1028]  current h, padded rows
    float* z_s = h_s + 8 * 1028;         // [4][64]    gate exchange
    float* c_s = z_s + 256;              // [64]       cell state (b*8+f)

    const int tid = threadIdx.x;
    const int bk  = blockIdx.x;
    const int f0  = bk * 8;

    // Load Wh slice (transposed to column-major rows): whs[c][k] = Wh[k][colg]
    for (int idx = tid; idx < 32 * 1024; idx += 256) {
        int k = idx >> 5;
        int c = idx & 31;
        int colg = (c >> 3) * FF + f0 + (c & 7);
        whs[c * 1028 + k] = Wh[(size_t)k * GG + colg];
    }
    if (tid < 64) {
        int b = tid >> 3, ff = tid & 7;
        g_h[0][b][f0 + ff] = 0.f;
        c_s[tid] = 0.f;
    }

    unsigned gen = *((volatile unsigned*)&g_gen);

    // barrier 0: init complete
    __threadfence();
    __syncthreads();
    if (tid == 0) {
        if (atomicAdd(&g_count, 1) == NB - 1) {
            atomicExch(&g_count, 0);
            __threadfence();
            atomicExch(&g_gen, gen + 1);
        } else {
            while (*((volatile unsigned*)&g_gen) == gen) {}
        }
        __threadfence();
    }
    __syncthreads();
    gen++;

    const int lane = tid & 31;
    const int w    = tid >> 5;
    const int b    = lane >> 2;            // 0..7 batch
    const int cq   = lane & 3;
    const int cloc = w * 4 + cq;           // 0..31 local gate-column
    const int colg = (cloc >> 3) * FF + f0 + (cloc & 7);

    int p = 0;
    for (int t = 0; t < TS; ++t) {
        // stage h into smem (padded rows: conflict-free)
        for (int i = tid; i < BSZ * 256; i += 256) {
            int bb = i >> 8;
            int kq = i & 255;
            float4 v = *((const float4*)&g_h[p][bb][kq << 2]);
            *(float4*)&h_s[bb * 1028 + (kq << 2)] = v;
        }
        __syncthreads();

        // z[b][cloc] = xw + h . Wh[:,colg]
        float acc0 = g_xw[(size_t)(b * TS + t) * GG + colg];
        float acc1 = 0.f, acc2 = 0.f, acc3 = 0.f;
        const float4* hv = (const float4*)&h_s[b * 1028];
        const float4* wv = (const float4*)&whs[cloc * 1028];
        #pragma unroll 4
        for (int kk = 0; kk < 256; ++kk) {
            float4 h4 = hv[kk];
            float4 w4 = wv[kk];
            acc0 += h4.x * w4.x;
            acc1 += h4.y * w4.y;
            acc2 += h4.z * w4.z;
            acc3 += h4.w * w4.w;
        }
        z_s[(cloc >> 3) * 64 + b * 8 + (cloc & 7)] = (acc0 + acc1) + (acc2 + acc3);
        __syncthreads();

        if (tid < 64) {   // one thread per (b, feature): gate math
            float zi = z_s[tid];
            float zf = z_s[64 + tid];
            float zg = z_s[128 + tid];
            float zo = z_s[192 + tid];
            float cold = c_s[tid];
            float si = 1.f / (1.f + expf(-zi));
            float sf = 1.f / (1.f + expf(-zf));
            float so = 1.f / (1.f + expf(-zo));
            float cn = sf * cold + si * tanhf(zg);
            float hn = so * tanhf(cn);
            c_s[tid] = cn;
            int bb = tid >> 3, ff = tid & 7;
            g_h[p ^ 1][bb][f0 + ff] = hn;
            g_hs[(size_t)(bb * TS + t) * FF + f0 + ff] = hn;
        }

        // global barrier: h[p^1] complete everywhere before next step reads it
        __threadfence();
        __syncthreads();
        if (tid == 0) {
            if (atomicAdd(&g_count, 1) == NB - 1) {
                atomicExch(&g_count, 0);
                __threadfence();
                atomicExch(&g_gen, gen + 1);
            } else {
                while (*((volatile unsigned*)&g_gen) == gen) {}
            }
            __threadfence();
        }
        __syncthreads();
        gen++;
        p ^= 1;
    }
}

// ---------------- launch ------------------------------------------------------
extern "C" void kernel_launch(void* const* d_in, const int* in_sizes, int n_in,
                              void* d_out, int out_size)
{
    const int*   tokens = (const int*)  d_in[0];
    const float* embed  = (const float*)d_in[1];
    const float* Wx     = (const float*)d_in[2];
    const float* Wh     = (const float*)d_in[3];
    const float* bgate  = (const float*)d_in[4];
    const float* Wd     = (const float*)d_in[5];
    const float* bd     = (const float*)d_in[6];
    float* out = (float*)d_out;

    void* xw_p = 0; cudaGetSymbolAddress(&xw_p, g_xw);
    void* hs_p = 0; cudaGetSymbolAddress(&hs_p, g_hs);

    cudaFuncSetAttribute(lstm_scan, cudaFuncAttributeMaxDynamicSharedMemorySize,
                         SMEM_BYTES);

    // 1) xW = embed[tokens] @ Wx + b   (M=4096, N=4096, K=1024)
    sgemm128<<<dim3(GG / 128, MM / 128), 256>>>(
        nullptr, tokens, embed, Wx, bgate, (float*)xw_p, MM, GG, FF);

    // 2) LSTM scan over T=512 (persistent, Wh resident in SMEM)
    lstm_scan<<<NB, 256, SMEM_BYTES>>>(Wh);

    // 3) logits = hs @ Wd + bd        (M=4096, N=32000, K=1024)
    sgemm128<<<dim3(VV / 128, MM / 128), 256>>>(
        (const float*)hs_p, nullptr, nullptr, Wd, bd, out, MM, VV, FF);
}

// round 3
// speedup vs baseline: 1.8735x; 1.8735x over previous
#include <cuda_runtime.h>

#define TS 512
#define BSZ 8
#define FF 1024
#define GG 4096      // 4F
#define VV 32000
#define MM (BSZ*TS)  // 4096
#define NB 128       // persistent scan blocks (1/SM via smem footprint)

// ---------------- scratch (device globals: no runtime allocation) -------------
__device__ float g_xw[(size_t)MM * GG];   // 64 MB: precomputed x@Wx + b
__device__ float g_hs[(size_t)MM * FF];   // 16 MB: hidden states per (b,t)
__device__ float g_h[2][BSZ][FF];         // ping-pong hidden state
__device__ unsigned g_count;              // barrier arrival counter
__device__ unsigned g_gen;                // barrier generation

// ---------------- generic fp32 SGEMM: C[M,N] = A[M,K] @ B[K,N] + bias ---------
__global__ void sgemm128(const float* __restrict__ A,
                         const int*   __restrict__ tokens,
                         const float* __restrict__ embed,
                         const float* __restrict__ Bm,
                         const float* __restrict__ bias,
                         float* __restrict__ C,
                         int M, int N, int K)
{
    __shared__ float As[8][128];
    __shared__ float Bs[8][128];
    const int tid = threadIdx.x;
    const int bn = blockIdx.x * 128;
    const int bm = blockIdx.y * 128;
    const int tm = tid >> 4;          // 0..15
    const int tn = tid & 15;          // 0..15

    const int arow = tid >> 1;        // 0..127
    const int ak   = (tid & 1) << 2;  // 0 or 4
    const int brow = tid >> 5;        // 0..7
    const int bcol = (tid & 31) << 2; // 0..124

    const float* Arow = tokens
        ? (embed + (size_t)tokens[bm + arow] * K)
        : (A + (size_t)(bm + arow) * K);
    const float* Bptr = Bm + (size_t)brow * N + bn + bcol;

    float acc[8][8];
    #pragma unroll
    for (int i = 0; i < 8; i++)
        #pragma unroll
        for (int j = 0; j < 8; j++) acc[i][j] = 0.f;

    float4 av = *(const float4*)(Arow + ak);
    float4 bv = *(const float4*)(Bptr);

    for (int kt = 0; kt < K; kt += 8) {
        As[ak+0][arow] = av.x; As[ak+1][arow] = av.y;
        As[ak+2][arow] = av.z; As[ak+3][arow] = av.w;
        *(float4*)&Bs[brow][bcol] = bv;
        __syncthreads();
        if (kt + 8 < K) {
            av = *(const float4*)(Arow + kt + 8 + ak);
            bv = *(const float4*)(Bptr + (size_t)(kt + 8) * N);
        }
        #pragma unroll
        for (int kk = 0; kk < 8; ++kk) {
            float a[8], b[8];
            *(float4*)(a)     = *(const float4*)&As[kk][tm * 4];
            *(float4*)(a + 4) = *(const float4*)&As[kk][64 + tm * 4];
            *(float4*)(b)     = *(const float4*)&Bs[kk][tn * 4];
            *(float4*)(b + 4) = *(const float4*)&Bs[kk][64 + tn * 4];
            #pragma unroll
            for (int i = 0; i < 8; i++)
                #pragma unroll
                for (int j = 0; j < 8; j++)
                    acc[i][j] += a[i] * b[j];
        }
        __syncthreads();
    }

    #pragma unroll
    for (int i = 0; i < 8; i++) {
        int row = bm + ((i < 4) ? (tm * 4 + i) : (64 + tm * 4 + (i - 4)));
        float* Cr = C + (size_t)row * N + bn;
        #pragma unroll
        for (int jh = 0; jh < 2; ++jh) {
            int col0 = jh * 64 + tn * 4;
            float4 v;
            v.x = acc[i][jh*4+0] + bias[bn + col0 + 0];
            v.y = acc[i][jh*4+1] + bias[bn + col0 + 1];
            v.z = acc[i][jh*4+2] + bias[bn + col0 + 2];
            v.w = acc[i][jh*4+3] + bias[bn + col0 + 3];
            *(float4*)(Cr + col0) = v;
        }
    }
}

// ---------------- persistent LSTM scan (register-reuse version) ---------------
// 128 blocks x 256 threads, 1 block/SM. Block bk owns features [bk*8, bk*8+8)
// -> 32 gate columns resident in SMEM as whs[k][c] (k-major, conflict-free).
// Warp w handles k-slice [w*128, w*128+128): lane c keeps acc[8] (8 batches),
// per 4-k group: 4 conflict-free w-loads + 8 broadcast h-float4 -> 32 FFMA.
// Cross-warp reduce in smem, 64-thread gate math, 1 global barrier/step.
//
// SMEM floats: whs 32768 + h_s 8192 + zp 2048 + z_s 256 + c_s 64 = 43328
#define SMEM_BYTES (43328 * 4)

__global__ void __launch_bounds__(256, 1) lstm_scan(const float* __restrict__ Wh)
{
    extern __shared__ float sm[];
    float* whs = sm;                 // [1024][32]
    float* h_s = sm + 32768;         // [8][1024]
    float* zp  = h_s + 8192;         // [8][256]  partial sums (w, c*8+b)
    float* z_s = zp + 2048;          // [256]     z by (gate*64 + b*8 + ff)
    float* c_s = z_s + 256;          // [64]      cell state (b*8+ff)

    const int tid = threadIdx.x;
    const int bk  = blockIdx.x;
    const int f0  = bk * 8;

    // Load Wh slice, k-major: whs[k*32+c] = Wh[k][(c>>3)*FF + f0 + (c&7)]
    for (int idx = tid; idx < 32768; idx += 256) {
        int k = idx >> 5;
        int c = idx & 31;
        int colg = (c >> 3) * FF + f0 + (c & 7);
        whs[idx] = Wh[(size_t)k * GG + colg];
    }
    if (tid < 64) {
        int b = tid >> 3, ff = tid & 7;
        g_h[0][b][f0 + ff] = 0.f;
        c_s[tid] = 0.f;
    }

    unsigned gen = *((volatile unsigned*)&g_gen);

    // barrier 0: init complete everywhere
    __threadfence();
    __syncthreads();
    if (tid == 0) {
        if (atomicAdd(&g_count, 1) == NB - 1) {
            atomicExch(&g_count, 0);
            __threadfence();
            atomicExch(&g_gen, gen + 1);
        } else {
            while (*((volatile unsigned*)&g_gen) == gen) {}
        }
        __threadfence();
    }
    __syncthreads();
    gen++;

    const int lane = tid & 31;       // gate-column c
    const int w    = tid >> 5;       // warp id = k-slice
    const int k0   = w * 128;

    // reducer-role mapping: tid -> (c, b)
    const int rc = tid >> 3;
    const int rb = tid & 7;
    const int r_colg = (rc >> 3) * FF + f0 + (rc & 7);
    const int r_zidx = (rc >> 3) * 64 + rb * 8 + (rc & 7);

    int p = 0;
    for (int t = 0; t < TS; ++t) {
        // issue xw LDG early (latency hidden behind FMA loop)
        float xwv = g_xw[(size_t)(rb * TS + t) * GG + r_colg];

        // stage h into smem: [8][1024]
        for (int i = tid; i < 2048; i += 256)
            ((float4*)h_s)[i] = ((const float4*)g_h[p])[i];
        __syncthreads();

        // partial z: lane's column over this warp's 128-k slice, 8 batches
        float acc[8];
        #pragma unroll
        for (int b = 0; b < 8; ++b) acc[b] = 0.f;

        #pragma unroll 4
        for (int kq = 0; kq < 128; kq += 4) {
            const int k = k0 + kq;
            const float* wp = whs + k * 32 + lane;
            float w0 = wp[0], w1 = wp[32], w2 = wp[64], w3 = wp[96];
            #pragma unroll
            for (int b = 0; b < 8; ++b) {
                float4 h4 = *(const float4*)&h_s[b * 1024 + k];
                acc[b] += h4.x * w0 + h4.y * w1 + h4.z * w2 + h4.w * w3;
            }
        }
        #pragma unroll
        for (int b = 0; b < 8; ++b)
            zp[w * 256 + lane * 8 + b] = acc[b];
        __syncthreads();

        // reduce 8 partials per output, add xw, scatter to gate layout
        {
            float s = xwv;
            #pragma unroll
            for (int ww = 0; ww < 8; ++ww) s += zp[ww * 256 + tid];
            z_s[r_zidx] = s;
        }
        __syncthreads();

        if (tid < 64) {   // gate math: one thread per (b, feature)
            float zi = z_s[tid];
            float zf = z_s[64 + tid];
            float zg = z_s[128 + tid];
            float zo = z_s[192 + tid];
            float cold = c_s[tid];
            float si = 1.f / (1.f + expf(-zi));
            float sf = 1.f / (1.f + expf(-zf));
            float so = 1.f / (1.f + expf(-zo));
            float cn = sf * cold + si * tanhf(zg);
            float hn = so * tanhf(cn);
            c_s[tid] = cn;
            int bb = tid >> 3, ff = tid & 7;
            g_h[p ^ 1][bb][f0 + ff] = hn;
            g_hs[(size_t)(bb * TS + t) * FF + f0 + ff] = hn;
        }

        // global barrier: h[p^1] complete everywhere before next step
        __threadfence();
        __syncthreads();
        if (tid == 0) {
            if (atomicAdd(&g_count, 1) == NB - 1) {
                atomicExch(&g_count, 0);
                __threadfence();
                atomicExch(&g_gen, gen + 1);
            } else {
                while (*((volatile unsigned*)&g_gen) == gen) {}
            }
            __threadfence();
        }
        __syncthreads();
        gen++;
        p ^= 1;
    }
}

// ---------------- launch ------------------------------------------------------
extern "C" void kernel_launch(void* const* d_in, const int* in_sizes, int n_in,
                              void* d_out, int out_size)
{
    const int*   tokens = (const int*)  d_in[0];
    const float* embed  = (const float*)d_in[1];
    const float* Wx     = (const float*)d_in[2];
    const float* Wh     = (const float*)d_in[3];
    const float* bgate  = (const float*)d_in[4];
    const float* Wd     = (const float*)d_in[5];
    const float* bd     = (const float*)d_in[6];
    float* out = (float*)d_out;

    void* xw_p = 0; cudaGetSymbolAddress(&xw_p, g_xw);
    void* hs_p = 0; cudaGetSymbolAddress(&hs_p, g_hs);

    cudaFuncSetAttribute(lstm_scan, cudaFuncAttributeMaxDynamicSharedMemorySize,
                         SMEM_BYTES);

    // 1) xW = embed[tokens] @ Wx + b   (M=4096, N=4096, K=1024)
    sgemm128<<<dim3(GG / 128, MM / 128), 256>>>(
        nullptr, tokens, embed, Wx, bgate, (float*)xw_p, MM, GG, FF);

    // 2) LSTM scan over T=512 (persistent, Wh resident in SMEM)
    lstm_scan<<<NB, 256, SMEM_BYTES>>>(Wh);

    // 3) logits = hs @ Wd + bd        (M=4096, N=32000, K=1024)
    sgemm128<<<dim3(VV / 128, MM / 128), 256>>>(
        (const float*)hs_p, nullptr, nullptr, Wd, bd, out, MM, VV, FF);
}

// round 7
// speedup vs baseline: 2.0616x; 1.1004x over previous
#include <cuda_runtime.h>
#include <cstdint>

#define TS 512
#define BSZ 8
#define FF 1024
#define GG 4096      // 4F
#define VV 32000
#define MM (BSZ*TS)  // 4096
#define NB 128       // persistent scan blocks

// ---------------- scratch (device globals: no runtime allocation) -------------
__device__ float g_xw[(size_t)MM * GG];   // 64 MB: precomputed x@Wx + b
__device__ float g_hs[(size_t)MM * FF];   // 16 MB: hidden states per (b,t)
__device__ float g_h[2][BSZ][FF];         // ping-pong hidden state
__device__ int g_flags[NB];               // distributed barrier flags
__device__ unsigned g_count;              // init-barrier counter
__device__ unsigned g_gen;                // init-barrier generation

// ---------------- packed f32x2 helpers (Blackwell family-wide PTX) ------------
typedef unsigned long long u64t;
__device__ __forceinline__ u64t pack2(float x, float y) {
    u64t r; asm("mov.b64 %0, {%1, %2};" : "=l"(r) : "f"(x), "f"(y)); return r;
}
__device__ __forceinline__ void fma2(u64t& d, u64t a, u64t b) {
    asm("fma.rn.f32x2 %0, %1, %2, %0;" : "+l"(d) : "l"(a), "l"(b));
}
__device__ __forceinline__ float2 unpack2(u64t v) {
    float2 f; asm("mov.b64 {%0, %1}, %2;" : "=f"(f.x), "=f"(f.y) : "l"(v)); return f;
}

// ---------------- fp32 SGEMM via FFMA2: C[M,N] = A[M,K] @ B[K,N] + bias -------
// 128x128 tile, Ktile=8, 256 threads, 8x8 microtile held as 8x4 f32x2 pairs.
__global__ void sgemm128(const float* __restrict__ A,
                         const int*   __restrict__ tokens,
                         const float* __restrict__ embed,
                         const float* __restrict__ Bm,
                         const float* __restrict__ bias,
                         float* __restrict__ C,
                         int M, int N, int K)
{
    __shared__ float As[8][128];
    __shared__ float Bs[8][128];
    const int tid = threadIdx.x;
    const int bn = blockIdx.x * 128;
    const int bm = blockIdx.y * 128;
    const int tm = tid >> 4;          // 0..15
    const int tn = tid & 15;          // 0..15

    const int arow = tid >> 1;        // 0..127
    const int ak   = (tid & 1) << 2;  // 0 or 4
    const int brow = tid >> 5;        // 0..7
    const int bcol = (tid & 31) << 2; // 0..124

    const float* Arow = tokens
        ? (embed + (size_t)tokens[bm + arow] * K)
        : (A + (size_t)(bm + arow) * K);
    const float* Bptr = Bm + (size_t)brow * N + bn + bcol;

    u64t acc2[8][4];
    #pragma unroll
    for (int i = 0; i < 8; i++)
        #pragma unroll
        for (int j = 0; j < 4; j++) acc2[i][j] = 0ull;

    float4 av = *(const float4*)(Arow + ak);
    float4 bv = *(const float4*)(Bptr);

    for (int kt = 0; kt < K; kt += 8) {
        As[ak+0][arow] = av.x; As[ak+1][arow] = av.y;
        As[ak+2][arow] = av.z; As[ak+3][arow] = av.w;
        *(float4*)&Bs[brow][bcol] = bv;
        __syncthreads();
        if (kt + 8 < K) {
            av = *(const float4*)(Arow + kt + 8 + ak);
            bv = *(const float4*)(Bptr + (size_t)(kt + 8) * N);
        }
        #pragma unroll
        for (int kk = 0; kk < 8; ++kk) {
            float a[8];
            *(float4*)(a)     = *(const float4*)&As[kk][tm * 4];
            *(float4*)(a + 4) = *(const float4*)&As[kk][64 + tm * 4];
            float4 b0 = *(const float4*)&Bs[kk][tn * 4];
            float4 b1 = *(const float4*)&Bs[kk][64 + tn * 4];
            u64t bp[4];
            bp[0] = pack2(b0.x, b0.y);
            bp[1] = pack2(b0.z, b0.w);
            bp[2] = pack2(b1.x, b1.y);
            bp[3] = pack2(b1.z, b1.w);
            #pragma unroll
            for (int i = 0; i < 8; i++) {
                u64t ad = pack2(a[i], a[i]);
                #pragma unroll
                for (int j = 0; j < 4; j++)
                    fma2(acc2[i][j], ad, bp[j]);
            }
        }
        __syncthreads();
    }

    #pragma unroll
    for (int i = 0; i < 8; i++) {
        int row = bm + ((i < 4) ? (tm * 4 + i) : (64 + tm * 4 + (i - 4)));
        float* Cr = C + (size_t)row * N + bn;
        #pragma unroll
        for (int jh = 0; jh < 2; ++jh) {
            int col0 = jh * 64 + tn * 4;
            float2 p0 = unpack2(acc2[i][jh * 2 + 0]);
            float2 p1 = unpack2(acc2[i][jh * 2 + 1]);
            float4 v;
            v.x = p0.x + bias[bn + col0 + 0];
            v.y = p0.y + bias[bn + col0 + 1];
            v.z = p1.x + bias[bn + col0 + 2];
            v.w = p1.y + bias[bn + col0 + 3];
            *(float4*)(Cr + col0) = v;
        }
    }
}

// ---------------- persistent LSTM scan ---------------------------------------
// 128 blocks x 256 threads, 1 block/SM. Block bk owns features [bk*8, bk*8+8)
// -> 32 gate columns resident in SMEM k-major. Warp w covers k-slice of 128.
// FFMA2 accumulates (even-k, odd-k) partial pairs. Distributed flag barrier.
// SMEM floats: whs 32768 + h_s 8192 + zp 2048 + z_s 256 + c_s 64 = 43328
#define SCAN_SMEM (43328 * 4)

__global__ void __launch_bounds__(256, 1) lstm_scan(const float* __restrict__ Wh)
{
    extern __shared__ float sm[];
    float* whs = sm;                 // [1024][32]
    float* h_s = sm + 32768;         // [8][1024]
    float* zp  = h_s + 8192;         // [8][256]  partials (w, lane*8+b)
    float* z_s = zp + 2048;          // [256]     z by (gate*64 + b*8 + ff)
    float* c_s = z_s + 256;          // [64]      cell state (b*8+ff)

    const int tid = threadIdx.x;
    const int bk  = blockIdx.x;
    const int f0  = bk * 8;

    if (tid == 0) g_flags[bk] = 0;   // reset per launch (graph replays!)

    // Load Wh slice, k-major: whs[k*32+c] = Wh[k][(c>>3)*FF + f0 + (c&7)]
    for (int idx = tid; idx < 32768; idx += 256) {
        int k = idx >> 5;
        int c = idx & 31;
        int colg = (c >> 3) * FF + f0 + (c & 7);
        whs[idx] = Wh[(size_t)k * GG + colg];
    }
    if (tid < 64) {
        int b = tid >> 3, ff = tid & 7;
        g_h[0][b][f0 + ff] = 0.f;
        c_s[tid] = 0.f;
    }

    unsigned gen = *((volatile unsigned*)&g_gen);

    // init barrier: flag resets + h init visible everywhere
    __threadfence();
    __syncthreads();
    if (tid == 0) {
        if (atomicAdd(&g_count, 1) == NB - 1) {
            atomicExch(&g_count, 0);
            __threadfence();
            atomicExch(&g_gen, gen + 1);
        } else {
            while (*((volatile unsigned*)&g_gen) == gen) {}
        }
        __threadfence();
    }
    __syncthreads();

    const int lane = tid & 31;       // gate-column c
    const int w    = tid >> 5;       // warp id = k-slice
    const int k0   = w * 128;

    const int rc = tid >> 3;         // reducer column
    const int rb = tid & 7;          // reducer batch
    const int r_colg = (rc >> 3) * FF + f0 + (rc & 7);
    const int r_zidx = (rc >> 3) * 64 + rb * 8 + (rc & 7);

    int p = 0;
    for (int t = 0; t < TS; ++t) {
        float xwv = g_xw[(size_t)(rb * TS + t) * GG + r_colg];

        // stage h via L2 (cross-SM coherent)
        for (int i = tid; i < 2048; i += 256)
            ((float4*)h_s)[i] = __ldcg(((const float4*)g_h[p]) + i);
        __syncthreads();

        // partial z: lane's gate-column over this warp's 128-k slice, 8 batches
        u64t acc2[8];
        #pragma unroll
        for (int b = 0; b < 8; ++b) acc2[b] = 0ull;

        #pragma unroll 4
        for (int kq = 0; kq < 128; kq += 4) {
            const int k = k0 + kq;
            const float* wp = whs + k * 32 + lane;
            u64t w01 = pack2(wp[0],  wp[32]);
            u64t w23 = pack2(wp[64], wp[96]);
            #pragma unroll
            for (int b = 0; b < 8; ++b) {
                float4 h4 = *(const float4*)&h_s[b * 1024 + k];
                fma2(acc2[b], pack2(h4.x, h4.y), w01);
                fma2(acc2[b], pack2(h4.z, h4.w), w23);
            }
        }
        #pragma unroll
        for (int b = 0; b < 8; ++b) {
            float2 s = unpack2(acc2[b]);
            zp[w * 256 + lane * 8 + b] = s.x + s.y;
        }
        __syncthreads();

        // reduce 8 warp partials, add xw, scatter to gate layout
        {
            float s = xwv;
            #pragma unroll
            for (int ww = 0; ww < 8; ++ww) s += zp[ww * 256 + tid];
            z_s[r_zidx] = s;
        }
        __syncthreads();

        if (tid < 64) {   // gate math: one thread per (b, feature)
            float zi = z_s[tid];
            float zf = z_s[64 + tid];
            float zg = z_s[128 + tid];
            float zo = z_s[192 + tid];
            float cold = c_s[tid];
            float si = 1.f / (1.f + expf(-zi));
            float sf = 1.f / (1.f + expf(-zf));
            float so = 1.f / (1.f + expf(-zo));
            float cn = sf * cold + si * tanhf(zg);
            float hn = so * tanhf(cn);
            c_s[tid] = cn;
            int bb = tid >> 3, ff = tid & 7;
            g_h[p ^ 1][bb][f0 + ff] = hn;
            g_hs[(size_t)(bb * TS + t) * FF + f0 + ff] = hn;
        }

        // distributed-flag barrier: own flag via atomic, poll all 128
        __threadfence();
        __syncthreads();
        if (tid == 0) atomicExch(&g_flags[bk], t + 1);
        if (tid < NB) {
            while (((volatile int*)g_flags)[tid] < t + 1) {}
        }
        __threadfence();
        __syncthreads();
        p ^= 1;
    }
}

// ---------------- launch ------------------------------------------------------
extern "C" void kernel_launch(void* const* d_in, const int* in_sizes, int n_in,
                              void* d_out, int out_size)
{
    const int*   tokens = (const int*)  d_in[0];
    const float* embed  = (const float*)d_in[1];
    const float* Wx     = (const float*)d_in[2];
    const float* Wh     = (const float*)d_in[3];
    const float* bgate  = (const float*)d_in[4];
    const float* Wd     = (const float*)d_in[5];
    const float* bd     = (const float*)d_in[6];
    float* out = (float*)d_out;

    void* xw_p = 0; cudaGetSymbolAddress(&xw_p, g_xw);
    void* hs_p = 0; cudaGetSymbolAddress(&hs_p, g_hs);

    cudaFuncSetAttribute(lstm_scan, cudaFuncAttributeMaxDynamicSharedMemorySize,
                         SCAN_SMEM);

    // 1) xW = embed[tokens] @ Wx + b   (M=4096, N=4096, K=1024)
    sgemm128<<<dim3(GG / 128, MM / 128), 256>>>(
        nullptr, tokens, embed, Wx, bgate, (float*)xw_p, MM, GG, FF);

    // 2) LSTM scan over T=512 (persistent, Wh resident in SMEM)
    lstm_scan<<<NB, 256, SCAN_SMEM>>>(Wh);

    // 3) logits = hs @ Wd + bd        (M=4096, N=32000, K=1024)
    sgemm128<<<dim3(VV / 128, MM / 128), 256>>>(
        (const float*)hs_p, nullptr, nullptr, Wd, bd, out, MM, VV, FF);
}